// round 2
// baseline (speedup 1.0000x reference)
#include <cuda_runtime.h>

// GATBranch: B=32, T=256, J=21, C=3. 8192 frames, 21 nodes each.
// Layer1: 3->256 (4 heads x 64), Layer2: 256->128 (1 head).
// Fixed adjacency per frame: five 4-chains through node 0 + self loops.

static constexpr int FRAMES = 8192;
static constexpr int F2 = 128;

// Incoming edge lists per dst node (self-loop included, template-derived).
// __device__ so they are visible in device code; indices are compile-time
// (fully unrolled loops), so these fold to immediates in SASS.
__device__ constexpr int INCN[21] = {6,2,2,2,2,2,2,2,2,2,2,2,2,2,2,2,2,2,2,2,2};
__device__ constexpr int INC[21][6] = {
    {4,8,12,16,20,0},
    {0,1,0,0,0,0},{1,2,0,0,0,0},{2,3,0,0,0,0},{3,4,0,0,0,0},
    {0,5,0,0,0,0},{5,6,0,0,0,0},{6,7,0,0,0,0},{7,8,0,0,0,0},
    {0,9,0,0,0,0},{9,10,0,0,0,0},{10,11,0,0,0,0},{11,12,0,0,0,0},
    {0,13,0,0,0,0},{13,14,0,0,0,0},{14,15,0,0,0,0},{15,16,0,0,0,0},
    {0,17,0,0,0,0},{17,18,0,0,0,0},{18,19,0,0,0,0},{19,20,0,0,0,0}
};

// Per-frame pooled output scratch: [8192][128] fp32 = 4 MB.
__device__ float g_fr[FRAMES * F2];

__global__ __launch_bounds__(256) void gat_frame_kernel(
    const float* __restrict__ kp,   // [8192*21*3]
    const float* __restrict__ W1,   // [3,256]
    const float* __restrict__ a1s,  // [256] (4x64 flattened)
    const float* __restrict__ a1d,  // [256]
    const float* __restrict__ b1,   // [256]
    const float* __restrict__ W2,   // [256,128]
    const float* __restrict__ a2s,  // [128]
    const float* __restrict__ a2d,  // [128]
    const float* __restrict__ b2)   // [128]
{
    const int f = blockIdx.x;
    const int t = threadIdx.x;
    const int lane = t & 31;
    const int wid  = t >> 5;

    __shared__ float xk[21][3];
    __shared__ __align__(16) float h1s[21 * 256];  // layer1 h; later reused for layer2 h2 [21][128]
    __shared__ __align__(16) float x1s[21 * 256];  // layer1 output (relu)
    __shared__ float es1[21][4], ed1[21][4];
    __shared__ float reds[21][8], redd[21][8];
    __shared__ float es2[21], ed2[21];

    // ---- load keypoints for this frame ----
    if (t < 63) xk[t / 3][t % 3] = kp[f * 63 + t];
    const float w10 = W1[t], w11 = W1[256 + t], w12 = W1[512 + t];
    const float as1 = a1s[t], ad1 = a1d[t];
    __syncthreads();

    // ---- layer1 linear h1[j][t] + attention logits (per-head reductions) ----
    #pragma unroll
    for (int j = 0; j < 21; j++) {
        float v = fmaf(xk[j][0], w10, fmaf(xk[j][1], w11, xk[j][2] * w12));
        h1s[j * 256 + t] = v;
        float ps = v * as1, pd = v * ad1;
        #pragma unroll
        for (int o = 16; o; o >>= 1) {
            ps += __shfl_down_sync(0xffffffffu, ps, o);
            pd += __shfl_down_sync(0xffffffffu, pd, o);
        }
        if (lane == 0) { reds[j][wid] = ps; redd[j][wid] = pd; }
    }
    __syncthreads();
    if (t < 84) {  // head h of node j spans warps 2h, 2h+1
        int j = t >> 2, h = t & 3;
        es1[j][h] = reds[j][2 * h] + reds[j][2 * h + 1];
        ed1[j][h] = redd[j][2 * h] + redd[j][2 * h + 1];
    }
    __syncthreads();

    // ---- layer1 softmax-attention aggregation + bias + relu -> x1s ----
    {
        const int h = t >> 6;
        const float b1v = b1[t];
        #pragma unroll
        for (int j = 0; j < 21; j++) {
            const int cnt = INCN[j];
            const float edv = ed1[j][h];
            float e[6]; float m = -1e30f;
            #pragma unroll
            for (int i = 0; i < 6; i++) {
                if (i < cnt) {
                    float x = es1[INC[j][i]][h] + edv;
                    x = x > 0.f ? x : 0.2f * x;          // leaky_relu(0.2)
                    e[i] = x; m = fmaxf(m, x);
                }
            }
            float z = 0.f, acc = 0.f;
            #pragma unroll
            for (int i = 0; i < 6; i++) {
                if (i < cnt) {
                    float w = __expf(e[i] - m);
                    z += w;
                    acc = fmaf(w, h1s[INC[j][i] * 256 + t], acc);
                }
            }
            float o = acc / z + b1v;
            x1s[j * 256 + t] = o > 0.f ? o : 0.f;        // relu
        }
    }
    __syncthreads();

    // ---- layer2 GEMM: h2[j][c] = sum_k x1s[j][k] * W2[k][c]  (21x256x128) ----
    {
        const int c  = t & 127;
        const int jg = t >> 7;                            // 0/1 -> j = jg + 2i
        float acc[11];
        #pragma unroll
        for (int i = 0; i < 11; i++) acc[i] = 0.f;
        const float* xp = x1s + jg * 256;
        for (int k = 0; k < 256; k += 4) {
            const float w0  = W2[(k + 0) * 128 + c];
            const float w1  = W2[(k + 1) * 128 + c];
            const float w2v = W2[(k + 2) * 128 + c];
            const float w3  = W2[(k + 3) * 128 + c];
            #pragma unroll
            for (int i = 0; i < 11; i++) {
                if (jg + 2 * i < 21) {
                    float4 xv = *reinterpret_cast<const float4*>(xp + i * 512 + k);
                    acc[i] = fmaf(xv.x, w0, fmaf(xv.y, w1,
                             fmaf(xv.z, w2v, fmaf(xv.w, w3, acc[i]))));
                }
            }
        }
        // store h2 into reused h1s region as [21][128]
        #pragma unroll
        for (int i = 0; i < 11; i++) {
            int j = jg + 2 * i;
            if (j < 21) h1s[j * 128 + c] = acc[i];
        }
    }
    __syncthreads();

    // ---- layer2 attention logits (128-wide reduction, warps 0..3) ----
    if (t < 128) {
        const float a2sv = a2s[t], a2dv = a2d[t];
        #pragma unroll
        for (int j = 0; j < 21; j++) {
            float v = h1s[j * 128 + t];
            float ps = v * a2sv, pd = v * a2dv;
            #pragma unroll
            for (int o = 16; o; o >>= 1) {
                ps += __shfl_down_sync(0xffffffffu, ps, o);
                pd += __shfl_down_sync(0xffffffffu, pd, o);
            }
            if (lane == 0) { reds[j][wid] = ps; redd[j][wid] = pd; }
        }
    }
    __syncthreads();
    if (t < 21) {
        es2[t] = reds[t][0] + reds[t][1] + reds[t][2] + reds[t][3];
        ed2[t] = redd[t][0] + redd[t][1] + redd[t][2] + redd[t][3];
    }
    __syncthreads();

    // ---- layer2 aggregation + bias + relu + joint-mean ----
    if (t < 128) {
        const float b2v = b2[t];
        float frn = 0.f;
        #pragma unroll
        for (int j = 0; j < 21; j++) {
            const int cnt = INCN[j];
            const float edv = ed2[j];
            float e[6]; float m = -1e30f;
            #pragma unroll
            for (int i = 0; i < 6; i++) {
                if (i < cnt) {
                    float x = es2[INC[j][i]] + edv;
                    x = x > 0.f ? x : 0.2f * x;
                    e[i] = x; m = fmaxf(m, x);
                }
            }
            float z = 0.f, acc = 0.f;
            #pragma unroll
            for (int i = 0; i < 6; i++) {
                if (i < cnt) {
                    float w = __expf(e[i] - m);
                    z += w;
                    acc = fmaf(w, h1s[INC[j][i] * 128 + t], acc);
                }
            }
            float o = acc / z + b2v;
            frn += (o > 0.f ? o : 0.f);
        }
        g_fr[f * 128 + t] = frn * (1.0f / 21.0f);
    }
}

// Time pooling: out[b][n] = mean over 256 frames of g_fr[b*256+t][n]
__global__ __launch_bounds__(128) void pool_kernel(float* __restrict__ out)
{
    const int b = blockIdx.x, n = threadIdx.x;
    const float* p = g_fr + (size_t)b * 256 * 128 + n;
    float s = 0.f;
    #pragma unroll 8
    for (int t = 0; t < 256; t++) s += p[t * 128];
    out[b * 128 + n] = s * (1.0f / 256.0f);
}

extern "C" void kernel_launch(void* const* d_in, const int* in_sizes, int n_in,
                              void* d_out, int out_size)
{
    const float* kp  = (const float*)d_in[0];
    const float* W1  = (const float*)d_in[1];
    const float* a1s = (const float*)d_in[2];
    const float* a1d = (const float*)d_in[3];
    const float* b1  = (const float*)d_in[4];
    const float* W2  = (const float*)d_in[5];
    const float* a2s = (const float*)d_in[6];
    const float* a2d = (const float*)d_in[7];
    const float* b2  = (const float*)d_in[8];
    // d_in[9], d_in[10] = src/dst edge lists: fixed template, hardcoded above.
    (void)in_sizes; (void)n_in; (void)out_size;

    gat_frame_kernel<<<FRAMES, 256>>>(kp, W1, a1s, a1d, b1, W2, a2s, a2d, b2);
    pool_kernel<<<32, 128>>>((float*)d_out);
}

// round 8
// speedup vs baseline: 1.0545x; 1.0545x over previous
#include <cuda_runtime.h>

// GATBranch: B=32, T=256, J=21, C=3. 8192 frames, 21 nodes each.
// Layer1: 3->256 (4 heads x 64), Layer2: 256->128 (1 head).
// Fixed adjacency: five 4-chains through node 0 + self loops (hardcoded).

static constexpr int FRAMES = 8192;

// Incoming edge lists per dst node. Compile-time folded (unrolled indices).
__device__ constexpr int INCN[21] = {6,2,2,2,2,2,2,2,2,2,2,2,2,2,2,2,2,2,2,2,2};
__device__ constexpr int INC[21][6] = {
    {4,8,12,16,20,0},
    {0,1,0,0,0,0},{1,2,0,0,0,0},{2,3,0,0,0,0},{3,4,0,0,0,0},
    {0,5,0,0,0,0},{5,6,0,0,0,0},{6,7,0,0,0,0},{7,8,0,0,0,0},
    {0,9,0,0,0,0},{9,10,0,0,0,0},{10,11,0,0,0,0},{11,12,0,0,0,0},
    {0,13,0,0,0,0},{13,14,0,0,0,0},{14,15,0,0,0,0},{15,16,0,0,0,0},
    {0,17,0,0,0,0},{17,18,0,0,0,0},{18,19,0,0,0,0},{19,20,0,0,0,0}
};

// Global scratch (device arrays; no runtime allocation).
__device__ float g_fr[32 * 128 * 256];        // [b][n][t] pooled-per-frame, 4 MB
__device__ float g_w2as[256], g_w2ad[256];    // W2 @ a2s / a2d
__device__ float g_ws1s[12], g_ws1d[12];      // (W1 @ a1)[c][h], idx c*4+h
__device__ float4 g_w2t4[64 * 128];           // [q][c] = (W2[4q..4q+3][c]), 128 KB

__device__ __forceinline__ unsigned long long ffma2(unsigned long long a,
                                                    unsigned long long b,
                                                    unsigned long long c) {
    unsigned long long d;
    asm("fma.rn.f32x2 %0, %1, %2, %3;" : "=l"(d) : "l"(a), "l"(b), "l"(c));
    return d;
}

__device__ __forceinline__ float lrelu02(float x) {
    return x > 0.f ? x : 0.2f * x;
}

// ---------------- precompute kernel ----------------
// b in [0,256): g_w2as/ad[k];  b in [256,268): g_ws1*;  b in [268,332): W2 quad-pack.
__global__ __launch_bounds__(128) void pre_kernel(
    const float* __restrict__ W1, const float* __restrict__ a1s,
    const float* __restrict__ a1d, const float* __restrict__ W2,
    const float* __restrict__ a2s, const float* __restrict__ a2d)
{
    const int b = blockIdx.x, t = threadIdx.x;
    if (b >= 268) {                     // W2 transposed k-quad pack
        int q = b - 268;                // 0..63
        g_w2t4[q * 128 + t] = make_float4(
            W2[(4 * q + 0) * 128 + t], W2[(4 * q + 1) * 128 + t],
            W2[(4 * q + 2) * 128 + t], W2[(4 * q + 3) * 128 + t]);
        return;
    }
    const int lane = t & 31, wid = t >> 5;
    __shared__ float red[2][4];
    float ps = 0.f, pd = 0.f;
    if (b < 256) {                      // w2a[k], k = b
        float v = W2[b * 128 + t];
        ps = v * a2s[t];
        pd = v * a2d[t];
    } else if (t < 64) {                // ws1[c][h], id = b-256 = c*4+h
        int id = b - 256, c = id >> 2, h = id & 3;
        float v = W1[c * 256 + h * 64 + t];
        ps = v * a1s[h * 64 + t];
        pd = v * a1d[h * 64 + t];
    }
    #pragma unroll
    for (int o = 16; o; o >>= 1) {
        ps += __shfl_down_sync(0xffffffffu, ps, o);
        pd += __shfl_down_sync(0xffffffffu, pd, o);
    }
    if (lane == 0) { red[0][wid] = ps; red[1][wid] = pd; }
    __syncthreads();
    if (t == 0) {
        if (b < 256) {
            g_w2as[b] = red[0][0] + red[0][1] + red[0][2] + red[0][3];
            g_w2ad[b] = red[1][0] + red[1][1] + red[1][2] + red[1][3];
        } else {
            g_ws1s[b - 256] = red[0][0] + red[0][1];
            g_ws1d[b - 256] = red[1][0] + red[1][1];
        }
    }
}

// ---------------- main fused per-frame kernel ----------------
__global__ __launch_bounds__(256, 2) void gat_frame_kernel(
    const float* __restrict__ kp,   // [8192*21*3]
    const float* __restrict__ W1,   // [3,256]
    const float* __restrict__ b1,   // [256]
    const float* __restrict__ b2)   // [128]
{
    const int f = blockIdx.x;
    const int t = threadIdx.x;

    __shared__ float xk[21][3];
    __shared__ float h1s[21 * 256];               // layer1 h; reused for layer2 h2 [j*256+c]
    __shared__ __align__(16) float x1s[21 * 260]; // layer1 out, packed, stride 260
    __shared__ float w2as_s[256], w2ad_s[256];
    __shared__ float es1[21][4], ed1[21][4];
    __shared__ float alpha1[21][6][4];
    __shared__ float esred[2][21][4];
    __shared__ float es2v[21], ed2v[21];
    __shared__ float alpha2[21][6];

    // ---- loads ----
    if (t < 63) xk[t / 3][t % 3] = kp[f * 63 + t];
    w2as_s[t] = g_w2as[t];
    w2ad_s[t] = g_w2ad[t];
    const float w10 = W1[t], w11 = W1[256 + t], w12 = W1[512 + t];
    const float b1v = b1[t];
    __syncthreads();

    // ---- layer1 linear: h1[j][t] ----
    #pragma unroll
    for (int j = 0; j < 21; j++) {
        float v = fmaf(xk[j][0], w10, fmaf(xk[j][1], w11, xk[j][2] * w12));
        h1s[j * 256 + t] = v;
    }
    // ---- layer1 attention logits from xk @ (W1 a1) ----
    if (t < 84) {
        int j = t >> 2, h = t & 3;
        es1[j][h] = fmaf(xk[j][0], g_ws1s[h], fmaf(xk[j][1], g_ws1s[4 + h],
                         xk[j][2] * g_ws1s[8 + h]));
        ed1[j][h] = fmaf(xk[j][0], g_ws1d[h], fmaf(xk[j][1], g_ws1d[4 + h],
                         xk[j][2] * g_ws1d[8 + h]));
    }
    __syncthreads();

    // ---- layer1 softmax alphas (84 threads: one per (j,h)) ----
    if (t < 84) {
        int j = t >> 2, h = t & 3;
        float edv = ed1[j][h];
        if (j == 0) {
            float e[6]; float m = -1e30f;
            #pragma unroll
            for (int i = 0; i < 6; i++) {
                int s = (i < 5) ? 4 * (i + 1) : 0;
                e[i] = lrelu02(es1[s][h] + edv);
                m = fmaxf(m, e[i]);
            }
            float z = 0.f;
            #pragma unroll
            for (int i = 0; i < 6; i++) { e[i] = __expf(e[i] - m); z += e[i]; }
            float zi = 1.f / z;
            #pragma unroll
            for (int i = 0; i < 6; i++) alpha1[0][i][h] = e[i] * zi;
        } else {
            int s0 = ((j & 3) == 1) ? 0 : j - 1;
            float e0 = lrelu02(es1[s0][h] + edv);
            float e1 = lrelu02(es1[j][h] + edv);
            float m = fmaxf(e0, e1);
            e0 = __expf(e0 - m); e1 = __expf(e1 - m);
            float zi = 1.f / (e0 + e1);
            alpha1[j][0][h] = e0 * zi;
            alpha1[j][1][h] = e1 * zi;
        }
    }
    __syncthreads();

    // ---- layer1 aggregation + bias + relu -> x1s (packed) ----
    {
        const int h = t >> 6;
        #pragma unroll
        for (int j = 0; j < 21; j++) {
            float acc = 0.f;
            #pragma unroll
            for (int i = 0; i < 6; i++) {
                if (i < INCN[j])
                    acc = fmaf(alpha1[j][i][h], h1s[INC[j][i] * 256 + t], acc);
            }
            x1s[j * 260 + t] = fmaxf(acc + b1v, 0.f);
        }
    }
    __syncthreads();

    // ---- layer2 attention-logit partials: e2[j] = x1[j,:] . (W2 a2) ----
    if (t < 168) {
        int sd = (t >= 84) ? 1 : 0;
        int tt = t - sd * 84;
        int j = tt >> 2, part = tt & 3;
        const float* wv = sd ? w2ad_s : w2as_s;
        const float* xr = x1s + j * 260 + part * 64;
        const float* wp = wv + part * 64;
        float p = 0.f;
        #pragma unroll 8
        for (int kk = 0; kk < 64; kk++)
            p = fmaf(xr[kk], wp[kk], p);
        esred[sd][j][part] = p;
    }

    // ---- layer2 GEMM: h2[j][c] = sum_k x1[j][k] W2[k][c]  (f32x2 over k) ----
    {
        const int c  = t & 127;
        const int jg = t >> 7;                       // j = jg + 2i
        unsigned long long acc[11];
        #pragma unroll
        for (int i = 0; i < 11; i++) acc[i] = 0ull;
        const ulonglong2* Wp =
            reinterpret_cast<const ulonglong2*>(g_w2t4) + c;
        #pragma unroll 4
        for (int q = 0; q < 64; q++) {
            ulonglong2 w = Wp[q * 128];              // (W2[4q],W2[4q+1]),(W2[4q+2],W2[4q+3]) @ col c
            #pragma unroll
            for (int i = 0; i < 11; i++) {
                int j = jg + 2 * i;
                if (j < 21) {
                    ulonglong2 xv = *reinterpret_cast<const ulonglong2*>(
                        x1s + j * 260 + 4 * q);      // broadcast within warp
                    acc[i] = ffma2(xv.x, w.x, acc[i]);
                    acc[i] = ffma2(xv.y, w.y, acc[i]);
                }
            }
        }
        // reduce f32x2 lanes (even-k + odd-k partials) and store h2 into h1s buffer
        #pragma unroll
        for (int i = 0; i < 11; i++) {
            int j = jg + 2 * i;
            if (j < 21) {
                float lo = __uint_as_float((unsigned)(acc[i] & 0xffffffffull));
                float hi = __uint_as_float((unsigned)(acc[i] >> 32));
                h1s[j * 256 + c] = lo + hi;
            }
        }
    }
    __syncthreads();

    // ---- layer2 logit reduce + softmax alphas ----
    if (t < 21) {
        es2v[t] = (esred[0][t][0] + esred[0][t][1]) + (esred[0][t][2] + esred[0][t][3]);
        ed2v[t] = (esred[1][t][0] + esred[1][t][1]) + (esred[1][t][2] + esred[1][t][3]);
    }
    __syncthreads();
    if (t < 21) {
        int j = t;
        float edv = ed2v[j];
        if (j == 0) {
            float e[6]; float m = -1e30f;
            #pragma unroll
            for (int i = 0; i < 6; i++) {
                int s = (i < 5) ? 4 * (i + 1) : 0;
                e[i] = lrelu02(es2v[s] + edv);
                m = fmaxf(m, e[i]);
            }
            float z = 0.f;
            #pragma unroll
            for (int i = 0; i < 6; i++) { e[i] = __expf(e[i] - m); z += e[i]; }
            float zi = 1.f / z;
            #pragma unroll
            for (int i = 0; i < 6; i++) alpha2[0][i] = e[i] * zi;
        } else {
            int s0 = ((j & 3) == 1) ? 0 : j - 1;
            float e0 = lrelu02(es2v[s0] + edv);
            float e1 = lrelu02(es2v[j] + edv);
            float m = fmaxf(e0, e1);
            e0 = __expf(e0 - m); e1 = __expf(e1 - m);
            float zi = 1.f / (e0 + e1);
            alpha2[j][0] = e0 * zi;
            alpha2[j][1] = e1 * zi;
        }
    }
    __syncthreads();

    // ---- layer2 aggregation + bias + relu + joint-mean, write [b][n][t] ----
    if (t < 128) {
        const float b2v = b2[t];
        float frn = 0.f;
        #pragma unroll
        for (int j = 0; j < 21; j++) {
            float acc = 0.f;
            #pragma unroll
            for (int i = 0; i < 6; i++) {
                if (i < INCN[j])
                    acc = fmaf(alpha2[j][i], h1s[INC[j][i] * 256 + t], acc);
            }
            frn += fmaxf(acc + b2v, 0.f);
        }
        g_fr[((f >> 8) * 128 + t) * 256 + (f & 255)] = frn * (1.0f / 21.0f);
    }
}

// ---------------- time pooling: out[b][n] = mean_t g_fr[b][n][t] ----------------
__global__ __launch_bounds__(512) void pool_kernel(float* __restrict__ out)
{
    __shared__ float ps[4][128];
    const int b = blockIdx.x, t = threadIdx.x;
    const int n = t & 127, q = t >> 7;
    const float4* p = reinterpret_cast<const float4*>(
        g_fr + ((size_t)(b * 128 + n)) * 256 + q * 64);
    float s = 0.f;
    #pragma unroll
    for (int i = 0; i < 16; i++) {
        float4 v = p[i];
        s += (v.x + v.y) + (v.z + v.w);
    }
    ps[q][n] = s;
    __syncthreads();
    if (t < 128)
        out[b * 128 + t] =
            ((ps[0][t] + ps[1][t]) + (ps[2][t] + ps[3][t])) * (1.0f / 256.0f);
}

extern "C" void kernel_launch(void* const* d_in, const int* in_sizes, int n_in,
                              void* d_out, int out_size)
{
    const float* kp  = (const float*)d_in[0];
    const float* W1  = (const float*)d_in[1];
    const float* a1s = (const float*)d_in[2];
    const float* a1d = (const float*)d_in[3];
    const float* b1  = (const float*)d_in[4];
    const float* W2  = (const float*)d_in[5];
    const float* a2s = (const float*)d_in[6];
    const float* a2d = (const float*)d_in[7];
    const float* b2  = (const float*)d_in[8];
    // d_in[9], d_in[10] = src/dst edge lists: fixed template, hardcoded.
    (void)in_sizes; (void)n_in; (void)out_size;

    pre_kernel<<<332, 128>>>(W1, a1s, a1d, W2, a2s, a2d);
    gat_frame_kernel<<<FRAMES, 256>>>(kp, W1, b1, b2);
    pool_kernel<<<32, 512>>>((float*)d_out);
}

// round 10
// speedup vs baseline: 1.7615x; 1.6705x over previous
#include <cuda_runtime.h>
#include <cstdint>

// GATBranch: B=32, T=256, J=21, C=3. 8192 frames, 21 nodes each.
// Layer1: 3->256 (4 heads x 64), Layer2: 256->128 (1 head).
// Fixed adjacency: five 4-chains through node 0 + self loops (hardcoded).
// Round 9: layer-2 GEMM on tensor cores (tf32 mma.sync.m16n8k8), 4 frames/block.

static constexpr int FRAMES = 8192;
static constexpr int FPB = 4;
static constexpr int NBLK = FRAMES / FPB;   // 2048

__device__ constexpr int INCN[21] = {6,2,2,2,2,2,2,2,2,2,2,2,2,2,2,2,2,2,2,2,2};
__device__ constexpr int INC[21][6] = {
    {4,8,12,16,20,0},
    {0,1,0,0,0,0},{1,2,0,0,0,0},{2,3,0,0,0,0},{3,4,0,0,0,0},
    {0,5,0,0,0,0},{5,6,0,0,0,0},{6,7,0,0,0,0},{7,8,0,0,0,0},
    {0,9,0,0,0,0},{9,10,0,0,0,0},{10,11,0,0,0,0},{11,12,0,0,0,0},
    {0,13,0,0,0,0},{13,14,0,0,0,0},{14,15,0,0,0,0},{15,16,0,0,0,0},
    {0,17,0,0,0,0},{17,18,0,0,0,0},{18,19,0,0,0,0},{19,20,0,0,0,0}
};

// Global scratch (no runtime allocation).
__device__ float  g_fr[32 * 128 * 256];     // [b][n][t] pooled-per-frame, 4 MB
__device__ float  g_w2as[256], g_w2ad[256]; // W2 @ a2s / a2d (fp32)
__device__ float  g_ws1s[12],  g_ws1d[12];  // (W1 @ a1)[c][h], idx c*4+h
__device__ float2 g_w2f[16 * 32 * 32];      // tf32 B-fragments [(nt*32+ks)*32+lane], 128 KB

// ---- dynamic smem layout (float offsets) ----
static constexpr int SM_X1A   = 0;          // 24576 floats (96 KB); reused as h2 (stride 136)
static constexpr int SM_H1S   = 24576;      // 5376
static constexpr int SM_X1S   = 29952;      // 5376
static constexpr int SM_W2AS  = 35328;      // 256
static constexpr int SM_W2AD  = 35584;      // 256
static constexpr int SM_XK    = 35840;      // 64 (63 used)
static constexpr int SM_ES1   = 35904;      // 84
static constexpr int SM_ED1   = 35988;      // 84
static constexpr int SM_AL1   = 36072;      // 504 (21*6*4) [j*24+i*4+h]
static constexpr int SM_ESRED = 36576;      // 672 (4*2*21*4) [fi*168+sd*84+j*4+p]
static constexpr int SM_ES2   = 37248;      // 84 (4*21)
static constexpr int SM_ED2   = 37332;      // 84
static constexpr int SM_AL2   = 37416;      // 504 (4*21*6) [fi*126+j*6+i]
static constexpr int SM_TOTALF = 37920;
static constexpr int SMEM_BYTES = SM_TOTALF * 4;   // 151680

__device__ __forceinline__ float tf32r(float x) {
    unsigned u; asm("cvt.rna.tf32.f32 %0, %1;" : "=r"(u) : "f"(x));
    return __uint_as_float(u);
}

__device__ __forceinline__ void mma_tf32(float d[4], const unsigned a[4],
                                         const unsigned b0, const unsigned b1) {
    asm volatile(
        "mma.sync.aligned.m16n8k8.row.col.f32.tf32.tf32.f32 "
        "{%0,%1,%2,%3}, {%4,%5,%6,%7}, {%8,%9}, {%0,%1,%2,%3};"
        : "+f"(d[0]), "+f"(d[1]), "+f"(d[2]), "+f"(d[3])
        : "r"(a[0]), "r"(a[1]), "r"(a[2]), "r"(a[3]), "r"(b0), "r"(b1));
}

__device__ __forceinline__ float lrelu02(float x) { return x > 0.f ? x : 0.2f * x; }

// ---------------- precompute kernel ----------------
// b<256: g_w2as/ad[k]; b in [256,268): g_ws1*; b in [268,396): B-fragment pack.
__global__ __launch_bounds__(128) void pre_kernel(
    const float* __restrict__ W1, const float* __restrict__ a1s,
    const float* __restrict__ a1d, const float* __restrict__ W2,
    const float* __restrict__ a2s, const float* __restrict__ a2d)
{
    const int b = blockIdx.x, t = threadIdx.x;
    if (b >= 268) {                     // tf32 B-fragment packing
        int combo = (b - 268) * 4 + (t >> 5);   // nt*32 + ks, 0..511
        int lane = t & 31;
        int nt = combo >> 5, ks = combo & 31;
        int t4 = lane & 3, g = lane >> 2;
        float v0 = W2[(ks * 8 + t4) * 128 + nt * 8 + g];
        float v1 = W2[(ks * 8 + t4 + 4) * 128 + nt * 8 + g];
        g_w2f[combo * 32 + lane] = make_float2(tf32r(v0), tf32r(v1));
        return;
    }
    const int lane = t & 31, wid = t >> 5;
    __shared__ float red[2][4];
    float ps = 0.f, pd = 0.f;
    if (b < 256) {
        float v = W2[b * 128 + t];
        ps = v * a2s[t];
        pd = v * a2d[t];
    } else if (t < 64) {
        int id = b - 256, c = id >> 2, h = id & 3;
        float v = W1[c * 256 + h * 64 + t];
        ps = v * a1s[h * 64 + t];
        pd = v * a1d[h * 64 + t];
    }
    #pragma unroll
    for (int o = 16; o; o >>= 1) {
        ps += __shfl_down_sync(0xffffffffu, ps, o);
        pd += __shfl_down_sync(0xffffffffu, pd, o);
    }
    if (lane == 0) { red[0][wid] = ps; red[1][wid] = pd; }
    __syncthreads();
    if (t == 0) {
        if (b < 256) {
            g_w2as[b] = red[0][0] + red[0][1] + red[0][2] + red[0][3];
            g_w2ad[b] = red[1][0] + red[1][1] + red[1][2] + red[1][3];
        } else {
            g_ws1s[b - 256] = red[0][0] + red[0][1];
            g_ws1d[b - 256] = red[1][0] + red[1][1];
        }
    }
}

// ---------------- main kernel: 4 frames per block ----------------
__global__ __launch_bounds__(256, 1) void gat_frame_kernel(
    const float* __restrict__ kp,   // [8192*21*3]
    const float* __restrict__ W1,   // [3,256]
    const float* __restrict__ b1,   // [256]
    const float* __restrict__ b2)   // [128]
{
    extern __shared__ float sm[];
    float* x1a   = sm + SM_X1A;     // A fragments / later h2 (stride 136)
    float* h1s   = sm + SM_H1S;
    float* x1s   = sm + SM_X1S;
    float* w2as  = sm + SM_W2AS;
    float* w2ad  = sm + SM_W2AD;
    float* xk    = sm + SM_XK;
    float* es1   = sm + SM_ES1;
    float* ed1   = sm + SM_ED1;
    float* al1   = sm + SM_AL1;
    float* esred = sm + SM_ESRED;
    float* es2v  = sm + SM_ES2;
    float* ed2v  = sm + SM_ED2;
    float* al2   = sm + SM_AL2;

    const int t = threadIdx.x;
    const int f0 = blockIdx.x * FPB;

    // zero A-fragment buffer (covers M padding rows 84..95)
    {
        float4* p = reinterpret_cast<float4*>(x1a);
        #pragma unroll
        for (int i = 0; i < 24; i++)
            p[t + 256 * i] = make_float4(0.f, 0.f, 0.f, 0.f);
    }
    w2as[t] = g_w2as[t];
    w2ad[t] = g_w2ad[t];
    const float w10 = W1[t], w11 = W1[256 + t], w12 = W1[512 + t];
    const float b1v = b1[t];
    // thread-constant part of the A-fragment slot address
    const int TP = (t >> 3) * 128 + (t & 3) * 4 + ((t >> 2) & 1) * 2;

    // ---------------- layer 1, four frames ----------------
    #pragma unroll
    for (int fi = 0; fi < FPB; fi++) {
        __syncthreads();
        if (t < 63) xk[t] = kp[(f0 + fi) * 63 + t];
        __syncthreads();
        // h1 + layer1 logits
        #pragma unroll
        for (int j = 0; j < 21; j++) {
            float v = fmaf(xk[3 * j], w10, fmaf(xk[3 * j + 1], w11, xk[3 * j + 2] * w12));
            h1s[j * 256 + t] = v;
        }
        if (t < 84) {
            int j = t >> 2, h = t & 3;
            es1[j * 4 + h] = fmaf(xk[3 * j], g_ws1s[h],
                             fmaf(xk[3 * j + 1], g_ws1s[4 + h], xk[3 * j + 2] * g_ws1s[8 + h]));
            ed1[j * 4 + h] = fmaf(xk[3 * j], g_ws1d[h],
                             fmaf(xk[3 * j + 1], g_ws1d[4 + h], xk[3 * j + 2] * g_ws1d[8 + h]));
        }
        __syncthreads();
        // layer1 softmax alphas
        if (t < 84) {
            int j = t >> 2, h = t & 3;
            float edv = ed1[j * 4 + h];
            if (j == 0) {
                float e[6]; float m = -1e30f;
                #pragma unroll
                for (int i = 0; i < 6; i++) {
                    int s = (i < 5) ? 4 * (i + 1) : 0;
                    e[i] = lrelu02(es1[s * 4 + h] + edv);
                    m = fmaxf(m, e[i]);
                }
                float z = 0.f;
                #pragma unroll
                for (int i = 0; i < 6; i++) { e[i] = __expf(e[i] - m); z += e[i]; }
                float zi = 1.f / z;
                #pragma unroll
                for (int i = 0; i < 6; i++) al1[0 * 24 + i * 4 + h] = e[i] * zi;
            } else {
                int s0 = ((j & 3) == 1) ? 0 : j - 1;
                float e0 = lrelu02(es1[s0 * 4 + h] + edv);
                float e1 = lrelu02(es1[j * 4 + h] + edv);
                float m = fmaxf(e0, e1);
                e0 = __expf(e0 - m); e1 = __expf(e1 - m);
                float zi = 1.f / (e0 + e1);
                al1[j * 24 + 0 * 4 + h] = e0 * zi;
                al1[j * 24 + 1 * 4 + h] = e1 * zi;
            }
        }
        __syncthreads();
        // aggregation + bias + relu -> x1s rows (fp32) + x1a fragments (tf32)
        {
            const int h = t >> 6;
            #pragma unroll
            for (int j = 0; j < 21; j++) {
                float acc = 0.f;
                #pragma unroll
                for (int i = 0; i < 6; i++) {
                    if (i < INCN[j])
                        acc = fmaf(al1[j * 24 + i * 4 + h], h1s[INC[j][i] * 256 + t], acc);
                }
                float o = fmaxf(acc + b1v, 0.f);
                x1s[j * 256 + t] = o;
                const int m  = fi * 21 + j;             // compile-time
                const int mt = m >> 4, rm = m & 15;
                const int CONST = mt * 4096 + (rm & 7) * 16 + (rm >> 3);
                x1a[CONST + TP] = tf32r(o);
            }
        }
        __syncthreads();
        // layer2 logit partials (fp32): e2[j] = x1[j,:] . (W2 a2)
        if (t < 168) {
            int sd = (t >= 84) ? 1 : 0;
            int tt = t - sd * 84;
            int j = tt >> 2, part = tt & 3;
            const float* wv = sd ? w2ad : w2as;
            const float* xr = x1s + j * 256 + part * 64;
            const float* wp = wv + part * 64;
            float p = 0.f;
            #pragma unroll 8
            for (int kk = 0; kk < 64; kk++) p = fmaf(xr[kk], wp[kk], p);
            esred[fi * 168 + sd * 84 + j * 4 + part] = p;
        }
    }
    __syncthreads();

    // ---------------- layer2 GEMM: [96,256] @ [256,128], tf32 mma ----------------
    {
        const int wid = t >> 5, lane = t & 31;
        const int mtg = wid >> 2;              // 0..1 -> mtiles mtg*3+{0,1,2}
        const int ntg = wid & 3;               // 0..3 -> ntiles ntg*4+{0..3}
        float d[3][4][4];
        #pragma unroll
        for (int mi = 0; mi < 3; mi++)
            #pragma unroll
            for (int ni = 0; ni < 4; ni++)
                #pragma unroll
                for (int r = 0; r < 4; r++) d[mi][ni][r] = 0.f;

        const uint2* __restrict__ bf = reinterpret_cast<const uint2*>(g_w2f);
        #pragma unroll 4
        for (int ks = 0; ks < 32; ks++) {
            unsigned a[3][4];
            #pragma unroll
            for (int mi = 0; mi < 3; mi++) {
                float4 av = *reinterpret_cast<const float4*>(
                    x1a + ((mtg * 3 + mi) * 32 + ks) * 128 + lane * 4);
                a[mi][0] = __float_as_uint(av.x);
                a[mi][1] = __float_as_uint(av.y);
                a[mi][2] = __float_as_uint(av.z);
                a[mi][3] = __float_as_uint(av.w);
            }
            uint2 b[4];
            #pragma unroll
            for (int ni = 0; ni < 4; ni++)
                b[ni] = __ldg(bf + ((ntg * 4 + ni) * 32 + ks) * 32 + lane);
            #pragma unroll
            for (int mi = 0; mi < 3; mi++)
                #pragma unroll
                for (int ni = 0; ni < 4; ni++)
                    mma_tf32(d[mi][ni], a[mi], b[ni].x, b[ni].y);
        }
        __syncthreads();   // all x1a reads done before overwriting with h2
        // store D frags -> h2 (aliased onto x1a, row stride 136)
        const int g = lane >> 2, t4 = lane & 3;
        #pragma unroll
        for (int mi = 0; mi < 3; mi++) {
            #pragma unroll
            for (int ni = 0; ni < 4; ni++) {
                int m0 = (mtg * 3 + mi) * 16 + g;
                int c0 = (ntg * 4 + ni) * 8 + t4 * 2;
                *reinterpret_cast<float2*>(x1a + m0 * 136 + c0) =
                    make_float2(d[mi][ni][0], d[mi][ni][1]);
                *reinterpret_cast<float2*>(x1a + (m0 + 8) * 136 + c0) =
                    make_float2(d[mi][ni][2], d[mi][ni][3]);
            }
        }
    }
    __syncthreads();

    // ---------------- layer2 logits reduce + softmax alphas ----------------
    if (t < 84) {
        int fi = t / 21, j = t - fi * 21;
        const float* er = esred + fi * 168;
        es2v[t] = (er[j * 4] + er[j * 4 + 1]) + (er[j * 4 + 2] + er[j * 4 + 3]);
        ed2v[t] = (er[84 + j * 4] + er[84 + j * 4 + 1]) + (er[84 + j * 4 + 2] + er[84 + j * 4 + 3]);
    }
    __syncthreads();
    if (t < 84) {
        int fi = t / 21, j = t - fi * 21;
        const float* ev = es2v + fi * 21;
        float edv = ed2v[fi * 21 + j];
        float* av = al2 + fi * 126 + j * 6;
        if (j == 0) {
            float e[6]; float m = -1e30f;
            #pragma unroll
            for (int i = 0; i < 6; i++) {
                int s = (i < 5) ? 4 * (i + 1) : 0;
                e[i] = lrelu02(ev[s] + edv);
                m = fmaxf(m, e[i]);
            }
            float z = 0.f;
            #pragma unroll
            for (int i = 0; i < 6; i++) { e[i] = __expf(e[i] - m); z += e[i]; }
            float zi = 1.f / z;
            #pragma unroll
            for (int i = 0; i < 6; i++) av[i] = e[i] * zi;
        } else {
            int s0 = ((j & 3) == 1) ? 0 : j - 1;
            float e0 = lrelu02(ev[s0] + edv);
            float e1 = lrelu02(ev[j] + edv);
            float m = fmaxf(e0, e1);
            e0 = __expf(e0 - m); e1 = __expf(e1 - m);
            float zi = 1.f / (e0 + e1);
            av[0] = e0 * zi;
            av[1] = e1 * zi;
        }
    }
    __syncthreads();

    // ---------------- layer2 aggregation + relu + joint-mean ----------------
    {
        const int c = t & 127;
        const float b2v = b2[c];
        #pragma unroll
        for (int pass = 0; pass < 2; pass++) {
            int fi = pass * 2 + (t >> 7);
            const float* av = al2 + fi * 126;
            const float* h2 = x1a + (fi * 21) * 136;
            float frn = 0.f;
            #pragma unroll
            for (int j = 0; j < 21; j++) {
                float acc = 0.f;
                #pragma unroll
                for (int i = 0; i < 6; i++) {
                    if (i < INCN[j])
                        acc = fmaf(av[j * 6 + i], h2[INC[j][i] * 136 + c], acc);
                }
                frn += fmaxf(acc + b2v, 0.f);
            }
            int f = f0 + fi;
            g_fr[((f >> 8) * 128 + c) * 256 + (f & 255)] = frn * (1.0f / 21.0f);
        }
    }
}

// ---------------- time pooling ----------------
__global__ __launch_bounds__(512) void pool_kernel(float* __restrict__ out)
{
    __shared__ float ps[4][128];
    const int b = blockIdx.x, t = threadIdx.x;
    const int n = t & 127, q = t >> 7;
    const float4* p = reinterpret_cast<const float4*>(
        g_fr + ((size_t)(b * 128 + n)) * 256 + q * 64);
    float s = 0.f;
    #pragma unroll
    for (int i = 0; i < 16; i++) {
        float4 v = p[i];
        s += (v.x + v.y) + (v.z + v.w);
    }
    ps[q][n] = s;
    __syncthreads();
    if (t < 128)
        out[b * 128 + t] =
            ((ps[0][t] + ps[1][t]) + (ps[2][t] + ps[3][t])) * (1.0f / 256.0f);
}

extern "C" void kernel_launch(void* const* d_in, const int* in_sizes, int n_in,
                              void* d_out, int out_size)
{
    const float* kp  = (const float*)d_in[0];
    const float* W1  = (const float*)d_in[1];
    const float* a1s = (const float*)d_in[2];
    const float* a1d = (const float*)d_in[3];
    const float* b1  = (const float*)d_in[4];
    const float* W2  = (const float*)d_in[5];
    const float* a2s = (const float*)d_in[6];
    const float* a2d = (const float*)d_in[7];
    const float* b2  = (const float*)d_in[8];
    // d_in[9], d_in[10] = src/dst edge lists: fixed template, hardcoded.
    (void)in_sizes; (void)n_in; (void)out_size;

    cudaFuncSetAttribute(gat_frame_kernel,
                         cudaFuncAttributeMaxDynamicSharedMemorySize, SMEM_BYTES);

    pre_kernel<<<396, 128>>>(W1, a1s, a1d, W2, a2s, a2d);
    gat_frame_kernel<<<NBLK, 256, SMEM_BYTES>>>(kp, W1, b1, b2);
    pool_kernel<<<32, 512>>>((float*)d_out);
}

// round 12
// speedup vs baseline: 3.6580x; 2.0766x over previous
#include <cuda_runtime.h>
#include <cstdint>

// GATBranch: B=32, T=256, J=21, C=3. 8192 frames, 21 nodes each.
// Layer1: 3->256 (4 heads x 64), Layer2: 256->128 (1 head).
// Fixed adjacency: five 4-chains through node 0 + self loops (hardcoded).
// Round 11: layer-1 algebraically collapsed (aggregate-then-project),
// x1 kept ONLY as tf32 A-fragments, 2 CTAs/SM, tf32 mma GEMM.

static constexpr int FRAMES = 8192;
static constexpr int FPB = 4;
static constexpr int NBLK = FRAMES / FPB;   // 2048

__device__ constexpr int INCN[21] = {6,2,2,2,2,2,2,2,2,2,2,2,2,2,2,2,2,2,2,2,2};
__device__ constexpr int INC[21][6] = {
    {4,8,12,16,20,0},
    {0,1,0,0,0,0},{1,2,0,0,0,0},{2,3,0,0,0,0},{3,4,0,0,0,0},
    {0,5,0,0,0,0},{5,6,0,0,0,0},{6,7,0,0,0,0},{7,8,0,0,0,0},
    {0,9,0,0,0,0},{9,10,0,0,0,0},{10,11,0,0,0,0},{11,12,0,0,0,0},
    {0,13,0,0,0,0},{13,14,0,0,0,0},{14,15,0,0,0,0},{15,16,0,0,0,0},
    {0,17,0,0,0,0},{17,18,0,0,0,0},{18,19,0,0,0,0},{19,20,0,0,0,0}
};

// Global scratch (no runtime allocation).
__device__ float  g_fr[32 * 128 * 256];     // [b][n][t] pooled-per-frame, 4 MB
__device__ float  g_w2as[256], g_w2ad[256]; // W2 @ a2s / a2d (fp32)
__device__ float  g_ws1s[12],  g_ws1d[12];  // (W1 @ a1)[c][h], idx c*4+h
__device__ float2 g_w2f[16 * 32 * 32];      // tf32 B-fragments [(nt*32+ks)*32+lane], 128 KB

// ---- dynamic smem layout (float offsets) ----
static constexpr int SM_X1A   = 0;          // 24576 (96 KB): A-frags / later h2 (stride 136)
static constexpr int SM_W2AS  = 24576;      // 256
static constexpr int SM_W2AD  = 24832;      // 256
static constexpr int SM_XK4   = 25088;      // 256 (252 used) [fi*63 + 3j + d]
static constexpr int SM_ES14  = 25344;      // 336 [fi*84 + j*4 + h]
static constexpr int SM_ED14  = 25680;      // 336
static constexpr int SM_Y4    = 26016;      // 1008 [fi*252 + (j*4+h)*3 + d]
static constexpr int SM_ESRED = 27024;      // 672 [fi*168 + sd*84 + j*4 + p]
static constexpr int SM_ES2   = 27696;      // 84
static constexpr int SM_ED2   = 27780;      // 84
static constexpr int SM_AL2   = 27864;      // 504 [fi*126 + j*6 + i]
static constexpr int SM_TOTALF = 28368;
static constexpr int SMEM_BYTES = SM_TOTALF * 4;   // 113472 -> 2 CTAs/SM

__device__ __forceinline__ float tf32r(float x) {
    unsigned u; asm("cvt.rna.tf32.f32 %0, %1;" : "=r"(u) : "f"(x));
    return __uint_as_float(u);
}

__device__ __forceinline__ void mma_tf32(float d[4], const unsigned a[4],
                                         const unsigned b0, const unsigned b1) {
    asm volatile(
        "mma.sync.aligned.m16n8k8.row.col.f32.tf32.tf32.f32 "
        "{%0,%1,%2,%3}, {%4,%5,%6,%7}, {%8,%9}, {%0,%1,%2,%3};"
        : "+f"(d[0]), "+f"(d[1]), "+f"(d[2]), "+f"(d[3])
        : "r"(a[0]), "r"(a[1]), "r"(a[2]), "r"(a[3]), "r"(b0), "r"(b1));
}

__device__ __forceinline__ float lrelu02(float x) { return x > 0.f ? x : 0.2f * x; }

// ---------------- precompute kernel ----------------
// b<256: g_w2as/ad[k]; b in [256,268): g_ws1*; b in [268,396): B-fragment pack.
__global__ __launch_bounds__(128) void pre_kernel(
    const float* __restrict__ W1, const float* __restrict__ a1s,
    const float* __restrict__ a1d, const float* __restrict__ W2,
    const float* __restrict__ a2s, const float* __restrict__ a2d)
{
    const int b = blockIdx.x, t = threadIdx.x;
    if (b >= 268) {                     // tf32 B-fragment packing
        int combo = (b - 268) * 4 + (t >> 5);   // nt*32 + ks, 0..511
        int lane = t & 31;
        int nt = combo >> 5, ks = combo & 31;
        int t4 = lane & 3, g = lane >> 2;
        float v0 = W2[(ks * 8 + t4) * 128 + nt * 8 + g];
        float v1 = W2[(ks * 8 + t4 + 4) * 128 + nt * 8 + g];
        g_w2f[combo * 32 + lane] = make_float2(tf32r(v0), tf32r(v1));
        return;
    }
    const int lane = t & 31, wid = t >> 5;
    __shared__ float red[2][4];
    float ps = 0.f, pd = 0.f;
    if (b < 256) {
        float v = W2[b * 128 + t];
        ps = v * a2s[t];
        pd = v * a2d[t];
    } else if (t < 64) {
        int id = b - 256, c = id >> 2, h = id & 3;
        float v = W1[c * 256 + h * 64 + t];
        ps = v * a1s[h * 64 + t];
        pd = v * a1d[h * 64 + t];
    }
    #pragma unroll
    for (int o = 16; o; o >>= 1) {
        ps += __shfl_down_sync(0xffffffffu, ps, o);
        pd += __shfl_down_sync(0xffffffffu, pd, o);
    }
    if (lane == 0) { red[0][wid] = ps; red[1][wid] = pd; }
    __syncthreads();
    if (t == 0) {
        if (b < 256) {
            g_w2as[b] = red[0][0] + red[0][1] + red[0][2] + red[0][3];
            g_w2ad[b] = red[1][0] + red[1][1] + red[1][2] + red[1][3];
        } else {
            g_ws1s[b - 256] = red[0][0] + red[0][1];
            g_ws1d[b - 256] = red[1][0] + red[1][1];
        }
    }
}

// ---------------- main kernel: 4 frames per block, 2 CTAs/SM ----------------
__global__ __launch_bounds__(256, 2) void gat_frame_kernel(
    const float* __restrict__ kp,   // [8192*21*3]
    const float* __restrict__ W1,   // [3,256]
    const float* __restrict__ b1,   // [256]
    const float* __restrict__ b2)   // [128]
{
    extern __shared__ float sm[];
    float* x1a   = sm + SM_X1A;
    float* w2as  = sm + SM_W2AS;
    float* w2ad  = sm + SM_W2AD;
    float* xk4   = sm + SM_XK4;
    float* es14  = sm + SM_ES14;
    float* ed14  = sm + SM_ED14;
    float* y4    = sm + SM_Y4;
    float* esred = sm + SM_ESRED;
    float* es2v  = sm + SM_ES2;
    float* ed2v  = sm + SM_ED2;
    float* al2   = sm + SM_AL2;

    const int t = threadIdx.x;
    const int f0 = blockIdx.x * FPB;

    // zero only the padding mtile (rows 84..95 live in mtile 5)
    {
        float4* p = reinterpret_cast<float4*>(x1a + 5 * 4096);
        #pragma unroll
        for (int i = 0; i < 4; i++) p[t + 256 * i] = make_float4(0.f, 0.f, 0.f, 0.f);
    }
    w2as[t] = g_w2as[t];
    w2ad[t] = g_w2ad[t];
    if (t < 252) xk4[t] = kp[f0 * 63 + t];     // 4 frames contiguous
    const float w10 = W1[t], w11 = W1[256 + t], w12 = W1[512 + t];
    const float b1v = b1[t];
    const int TP = (t >> 3) * 128 + (t & 3) * 4 + ((t >> 2) & 1) * 2;
    __syncthreads();

    // ---- phase B: layer1 logits for all 4 frames (336 tasks) ----
    #pragma unroll
    for (int u = t; u < 336; u += 256) {
        int fi = u / 84, r = u - fi * 84;
        int j = r >> 2, h = r & 3;
        const float* x = xk4 + fi * 63 + 3 * j;
        es14[u] = fmaf(x[0], g_ws1s[h], fmaf(x[1], g_ws1s[4 + h], x[2] * g_ws1s[8 + h]));
        ed14[u] = fmaf(x[0], g_ws1d[h], fmaf(x[1], g_ws1d[4 + h], x[2] * g_ws1d[8 + h]));
    }
    __syncthreads();

    // ---- phase C: softmax alphas + aggregated 3-vectors y (336 tasks) ----
    #pragma unroll
    for (int u = t; u < 336; u += 256) {
        int fi = u / 84, r = u - fi * 84;
        int j = r >> 2, h = r & 3;
        const float* es = es14 + fi * 84;
        const float* x  = xk4 + fi * 63;
        float edv = ed14[u];
        float y0 = 0.f, y1 = 0.f, y2 = 0.f;
        if (j == 0) {
            float e[6]; float m = -1e30f;
            #pragma unroll
            for (int i = 0; i < 6; i++) {
                int s = (i < 5) ? 4 * (i + 1) : 0;
                e[i] = lrelu02(es[s * 4 + h] + edv);
                m = fmaxf(m, e[i]);
            }
            float z = 0.f;
            #pragma unroll
            for (int i = 0; i < 6; i++) { e[i] = __expf(e[i] - m); z += e[i]; }
            float zi = 1.f / z;
            #pragma unroll
            for (int i = 0; i < 6; i++) {
                int s = (i < 5) ? 4 * (i + 1) : 0;
                float a = e[i] * zi;
                y0 = fmaf(a, x[3 * s], y0);
                y1 = fmaf(a, x[3 * s + 1], y1);
                y2 = fmaf(a, x[3 * s + 2], y2);
            }
        } else {
            int s0 = ((j & 3) == 1) ? 0 : j - 1;
            float e0 = lrelu02(es[s0 * 4 + h] + edv);
            float e1 = lrelu02(es[j * 4 + h] + edv);
            float m = fmaxf(e0, e1);
            e0 = __expf(e0 - m); e1 = __expf(e1 - m);
            float zi = 1.f / (e0 + e1);
            float a0 = e0 * zi, a1 = e1 * zi;
            y0 = fmaf(a0, x[3 * s0], a1 * x[3 * j]);
            y1 = fmaf(a0, x[3 * s0 + 1], a1 * x[3 * j + 1]);
            y2 = fmaf(a0, x[3 * s0 + 2], a1 * x[3 * j + 2]);
        }
        float* yp = y4 + fi * 252 + r * 3;
        yp[0] = y0; yp[1] = y1; yp[2] = y2;
    }
    __syncthreads();

    // ---- phase D: x1[m][c] = relu(y . W1col_c + b1), straight to tf32 A-frags ----
    {
        const int h = t >> 6;
        #pragma unroll
        for (int fi = 0; fi < FPB; fi++) {
            #pragma unroll
            for (int j = 0; j < 21; j++) {
                const float* yp = y4 + fi * 252 + (j * 4 + h) * 3;
                float o = fmaf(yp[0], w10, fmaf(yp[1], w11, fmaf(yp[2], w12, b1v)));
                o = fmaxf(o, 0.f);
                const int m  = fi * 21 + j;            // compile-time
                const int mt = m >> 4, rm = m & 15;
                const int CONST = mt * 4096 + (rm & 7) * 16 + (rm >> 3);
                x1a[CONST + TP] = tf32r(o);
            }
        }
    }
    __syncthreads();

    // ---- phase E: layer2 logit partials from A-frags (672 tasks, k = p mod 4) ----
    #pragma unroll
    for (int u = t; u < 672; u += 256) {
        int fi = u / 168, rr = u - fi * 168;
        int sd = rr / 84, r2 = rr - sd * 84;
        int j = r2 >> 2, p = r2 & 3;
        int m = fi * 21 + j;
        int mt = m >> 4, rm = m & 15;
        const float* xb = x1a + mt * 4096 + (rm & 7) * 16 + (rm >> 3) + 4 * p;
        const float* wv = (sd ? w2ad : w2as) + p;
        float s = 0.f;
        #pragma unroll
        for (int i = 0; i < 64; i++)
            s = fmaf(xb[(i >> 1) * 128 + (i & 1) * 2], wv[4 * i], s);
        esred[u] = s;
    }
    // (no sync needed: GEMM below reads x1a only; its internal pre-store
    //  sync orders phase-E reads before h2 overwrites x1a)

    // ---- layer2 GEMM: [96,256] @ [256,128], tf32 mma ----
    {
        const int wid = t >> 5, lane = t & 31;
        const int mtg = wid >> 2;              // 0..1 -> mtiles mtg*3+{0,1,2}
        const int ntg = wid & 3;               // 0..3 -> ntiles ntg*4+{0..3}
        float d[3][4][4];
        #pragma unroll
        for (int mi = 0; mi < 3; mi++)
            #pragma unroll
            for (int ni = 0; ni < 4; ni++)
                #pragma unroll
                for (int r = 0; r < 4; r++) d[mi][ni][r] = 0.f;

        const uint2* __restrict__ bf = reinterpret_cast<const uint2*>(g_w2f);
        #pragma unroll 4
        for (int ks = 0; ks < 32; ks++) {
            unsigned a[3][4];
            #pragma unroll
            for (int mi = 0; mi < 3; mi++) {
                float4 av = *reinterpret_cast<const float4*>(
                    x1a + ((mtg * 3 + mi) * 32 + ks) * 128 + lane * 4);
                a[mi][0] = __float_as_uint(av.x);
                a[mi][1] = __float_as_uint(av.y);
                a[mi][2] = __float_as_uint(av.z);
                a[mi][3] = __float_as_uint(av.w);
            }
            uint2 b[4];
            #pragma unroll
            for (int ni = 0; ni < 4; ni++)
                b[ni] = __ldg(bf + ((ntg * 4 + ni) * 32 + ks) * 32 + lane);
            #pragma unroll
            for (int mi = 0; mi < 3; mi++)
                #pragma unroll
                for (int ni = 0; ni < 4; ni++)
                    mma_tf32(d[mi][ni], a[mi], b[ni].x, b[ni].y);
        }
        __syncthreads();   // x1a reads (GEMM + phase E) done before h2 overwrite
        const int g = lane >> 2, t4 = lane & 3;
        #pragma unroll
        for (int mi = 0; mi < 3; mi++) {
            #pragma unroll
            for (int ni = 0; ni < 4; ni++) {
                int m0 = (mtg * 3 + mi) * 16 + g;
                int c0 = (ntg * 4 + ni) * 8 + t4 * 2;
                *reinterpret_cast<float2*>(x1a + m0 * 136 + c0) =
                    make_float2(d[mi][ni][0], d[mi][ni][1]);
                *reinterpret_cast<float2*>(x1a + (m0 + 8) * 136 + c0) =
                    make_float2(d[mi][ni][2], d[mi][ni][3]);
            }
        }
    }
    __syncthreads();

    // ---- layer2 logits reduce + softmax alphas ----
    if (t < 84) {
        int fi = t / 21, j = t - fi * 21;
        const float* er = esred + fi * 168;
        es2v[t] = (er[j * 4] + er[j * 4 + 1]) + (er[j * 4 + 2] + er[j * 4 + 3]);
        ed2v[t] = (er[84 + j * 4] + er[84 + j * 4 + 1]) + (er[84 + j * 4 + 2] + er[84 + j * 4 + 3]);
    }
    __syncthreads();
    if (t < 84) {
        int fi = t / 21, j = t - fi * 21;
        const float* ev = es2v + fi * 21;
        float edv = ed2v[fi * 21 + j];
        float* av = al2 + fi * 126 + j * 6;
        if (j == 0) {
            float e[6]; float m = -1e30f;
            #pragma unroll
            for (int i = 0; i < 6; i++) {
                int s = (i < 5) ? 4 * (i + 1) : 0;
                e[i] = lrelu02(ev[s] + edv);
                m = fmaxf(m, e[i]);
            }
            float z = 0.f;
            #pragma unroll
            for (int i = 0; i < 6; i++) { e[i] = __expf(e[i] - m); z += e[i]; }
            float zi = 1.f / z;
            #pragma unroll
            for (int i = 0; i < 6; i++) av[i] = e[i] * zi;
        } else {
            int s0 = ((j & 3) == 1) ? 0 : j - 1;
            float e0 = lrelu02(ev[s0] + edv);
            float e1 = lrelu02(ev[j] + edv);
            float m = fmaxf(e0, e1);
            e0 = __expf(e0 - m); e1 = __expf(e1 - m);
            float zi = 1.f / (e0 + e1);
            av[0] = e0 * zi;
            av[1] = e1 * zi;
        }
    }
    __syncthreads();

    // ---- layer2 aggregation + relu + joint-mean ----
    {
        const int c = t & 127;
        const float b2v = b2[c];
        #pragma unroll
        for (int pass = 0; pass < 2; pass++) {
            int fi = pass * 2 + (t >> 7);
            const float* av = al2 + fi * 126;
            const float* h2 = x1a + (fi * 21) * 136;
            float frn = 0.f;
            #pragma unroll
            for (int j = 0; j < 21; j++) {
                float acc = 0.f;
                #pragma unroll
                for (int i = 0; i < 6; i++) {
                    if (i < INCN[j])
                        acc = fmaf(av[j * 6 + i], h2[INC[j][i] * 136 + c], acc);
                }
                frn += fmaxf(acc + b2v, 0.f);
            }
            int f = f0 + fi;
            g_fr[((f >> 8) * 128 + c) * 256 + (f & 255)] = frn * (1.0f / 21.0f);
        }
    }
}

// ---------------- time pooling ----------------
__global__ __launch_bounds__(512) void pool_kernel(float* __restrict__ out)
{
    __shared__ float ps[4][128];
    const int b = blockIdx.x, t = threadIdx.x;
    const int n = t & 127, q = t >> 7;
    const float4* p = reinterpret_cast<const float4*>(
        g_fr + ((size_t)(b * 128 + n)) * 256 + q * 64);
    float s = 0.f;
    #pragma unroll
    for (int i = 0; i < 16; i++) {
        float4 v = p[i];
        s += (v.x + v.y) + (v.z + v.w);
    }
    ps[q][n] = s;
    __syncthreads();
    if (t < 128)
        out[b * 128 + t] =
            ((ps[0][t] + ps[1][t]) + (ps[2][t] + ps[3][t])) * (1.0f / 256.0f);
}

extern "C" void kernel_launch(void* const* d_in, const int* in_sizes, int n_in,
                              void* d_out, int out_size)
{
    const float* kp  = (const float*)d_in[0];
    const float* W1  = (const float*)d_in[1];
    const float* a1s = (const float*)d_in[2];
    const float* a1d = (const float*)d_in[3];
    const float* b1  = (const float*)d_in[4];
    const float* W2  = (const float*)d_in[5];
    const float* a2s = (const float*)d_in[6];
    const float* a2d = (const float*)d_in[7];
    const float* b2  = (const float*)d_in[8];
    // d_in[9], d_in[10] = src/dst edge lists: fixed template, hardcoded.
    (void)in_sizes; (void)n_in; (void)out_size;

    cudaFuncSetAttribute(gat_frame_kernel,
                         cudaFuncAttributeMaxDynamicSharedMemorySize, SMEM_BYTES);

    pre_kernel<<<396, 128>>>(W1, a1s, a1d, W2, a2s, a2d);
    gat_frame_kernel<<<NBLK, 256, SMEM_BYTES>>>(kp, W1, b1, b2);
    pool_kernel<<<32, 512>>>((float*)d_out);
}